// round 4
// baseline (speedup 1.0000x reference)
#include <cuda_runtime.h>
#include <cuda_bf16.h>
#include <cstdint>

// Problem constants (fixed by the reference)
#define N_NODES 50000
#define N_EDGES 800000
#define IN_CH   128
#define OUT_CH  64
#define SELF_LOOP_W 2.0f

// Scratch (device globals: no allocation allowed)
__device__ float g_deg[N_NODES];
__device__ float g_dinv[N_NODES];
__device__ float g_xw[N_NODES * OUT_CH];
__device__ float g_out[N_NODES * OUT_CH];
__device__ int   g_is64;   // 1 if edge_index arrived as int64, 0 if int32

// ---------------------------------------------------------------------------
// 0) Detect edge_index dtype. View the buffer as int32 words. For int64 input
//    (all values in [0, 50000) << 2^31), every odd word is the zero high-half.
//    For int32 input, odd words are random node indices — OR over 1024
//    samples is nonzero with overwhelming probability. Deterministic.
__global__ void detect_dtype_kernel(const unsigned* __restrict__ p32) {
    __shared__ unsigned red[256];
    unsigned acc = 0;
    // 1024 samples of odd words, spread over the first 800000 words
    // (safe in both layouts: int32 buffer = 1.6M words, int64 = 3.2M words).
#pragma unroll
    for (int j = 0; j < 4; j++) {
        int k = threadIdx.x * 4 + j;            // 0..1023
        int pos = 2 * (k * 390 + 1) + 1;        // odd positions < 800000
        acc |= p32[pos];
    }
    red[threadIdx.x] = acc;
    __syncthreads();
    for (int s = 128; s > 0; s >>= 1) {
        if (threadIdx.x < s) red[threadIdx.x] |= red[threadIdx.x + s];
        __syncthreads();
    }
    if (threadIdx.x == 0) g_is64 = (red[0] == 0) ? 1 : 0;
}

// Edge accessors (is64 loaded once per thread; uniform branch)
__device__ __forceinline__ int edge_src(const int* __restrict__ p32, int e, int is64) {
    int v = is64 ? p32[2 * e] : p32[e];
    return (unsigned)v < N_NODES ? v : 0;
}
__device__ __forceinline__ int edge_dst(const int* __restrict__ p32, int e, int is64) {
    int v = is64 ? p32[2 * (N_EDGES + e)] : p32[N_EDGES + e];
    return (unsigned)v < N_NODES ? v : 0;
}

// ---------------------------------------------------------------------------
// 1) deg init: start from the self-loop weight (2.0)
__global__ void deg_init_kernel() {
    int i = blockIdx.x * blockDim.x + threadIdx.x;
    if (i < N_NODES) g_deg[i] = SELF_LOOP_W;
}

// 2) deg accumulation: deg[col[e]] += ew[e]
__global__ void deg_accum_kernel(const int* __restrict__ ei,
                                 const float* __restrict__ ew) {
    int e = blockIdx.x * blockDim.x + threadIdx.x;
    if (e >= N_EDGES) return;
    int is64 = g_is64;
    int t = edge_dst(ei, e, is64);
    atomicAdd(&g_deg[t], ew[e]);
}

// 3) dinv = rsqrt(deg)
__global__ void dinv_kernel() {
    int i = blockIdx.x * blockDim.x + threadIdx.x;
    if (i >= N_NODES) return;
    float d = g_deg[i];
    g_dinv[i] = d > 0.0f ? rsqrtf(d) : 0.0f;
}

// ---------------------------------------------------------------------------
// 4) GEMM: xw[N,64] = x[N,128] @ W[128,64], fp32, smem-tiled.
#define GEMM_ROWS 64
#define XS_STRIDE 132
__global__ __launch_bounds__(256) void gemm_kernel(const float* __restrict__ x,
                                                   const float* __restrict__ W) {
    __shared__ float Ws[IN_CH * OUT_CH];        // 32KB
    __shared__ float Xs[GEMM_ROWS * XS_STRIDE]; // ~33KB
    int node0 = blockIdx.x * GEMM_ROWS;

    for (int i = threadIdx.x; i < IN_CH * OUT_CH / 4; i += 256)
        ((float4*)Ws)[i] = ((const float4*)W)[i];

    for (int i = threadIdx.x; i < GEMM_ROWS * (IN_CH / 4); i += 256) {
        int r = i / (IN_CH / 4);
        int c = i % (IN_CH / 4);
        int node = node0 + r;
        float4 v = make_float4(0.f, 0.f, 0.f, 0.f);
        if (node < N_NODES)
            v = ((const float4*)(x + (size_t)node * IN_CH))[c];
        float* dst = &Xs[r * XS_STRIDE + c * 4];
        dst[0] = v.x; dst[1] = v.y; dst[2] = v.z; dst[3] = v.w;
    }
    __syncthreads();

    int r    = threadIdx.x >> 2;   // 0..63 local row
    int cg   = threadIdx.x & 3;    // column group: cols cg + 4*j
    int node = node0 + r;

    float acc[16];
#pragma unroll
    for (int j = 0; j < 16; j++) acc[j] = 0.0f;

#pragma unroll 4
    for (int k = 0; k < IN_CH; k++) {
        float xv = Xs[r * XS_STRIDE + k];
#pragma unroll
        for (int j = 0; j < 16; j++)
            acc[j] += xv * Ws[k * OUT_CH + cg + 4 * j];
    }

    if (node < N_NODES) {
        float* o = g_xw + (size_t)node * OUT_CH;
#pragma unroll
        for (int j = 0; j < 16; j++)
            o[cg + 4 * j] = acc[j];
    }
}

// ---------------------------------------------------------------------------
// 5) out init (into g_out): self-loop term + bias.
__global__ void init_out_kernel(const float* __restrict__ b) {
    int idx = blockIdx.x * blockDim.x + threadIdx.x;   // N_NODES*16 float4 units
    int node = idx >> 4;
    int lane = idx & 15;
    if (node >= N_NODES) return;
    float d = g_dinv[node];
    float w = SELF_LOOP_W * d * d;
    float4 v  = ((const float4*)(g_xw + (size_t)node * OUT_CH))[lane];
    float4 bb = ((const float4*)b)[lane];
    float4 o  = make_float4(fmaf(v.x, w, bb.x), fmaf(v.y, w, bb.y),
                            fmaf(v.z, w, bb.z), fmaf(v.w, w, bb.w));
    ((float4*)(g_out + (size_t)node * OUT_CH))[lane] = o;
}

// ---------------------------------------------------------------------------
// 6) edge scatter (into g_out): out[col] += dinv[row]*ew*dinv[col] * xw[row]
//    16 threads per edge; each loads one float4 of xw and issues 4 scalar
//    atomicAdds to the device-resident accumulator.
__global__ __launch_bounds__(256) void scatter_kernel(const int* __restrict__ ei,
                                                      const float* __restrict__ ew) {
    int idx  = blockIdx.x * blockDim.x + threadIdx.x;
    int e    = idx >> 4;
    int lane = idx & 15;
    if (e >= N_EDGES) return;
    int is64 = g_is64;

    int s = edge_src(ei, e, is64);
    int t = edge_dst(ei, e, is64);
    float w = g_dinv[s] * ew[e] * g_dinv[t];

    float4 v = ((const float4*)(g_xw + (size_t)s * OUT_CH))[lane];
    float* p = g_out + (size_t)t * OUT_CH + lane * 4;
    atomicAdd(p + 0, v.x * w);
    atomicAdd(p + 1, v.y * w);
    atomicAdd(p + 2, v.z * w);
    atomicAdd(p + 3, v.w * w);
}

// ---------------------------------------------------------------------------
// 7) copy accumulator to d_out with plain stores.
__global__ void copy_out_kernel(float* __restrict__ out) {
    int i = blockIdx.x * blockDim.x + threadIdx.x;   // float4 units
    if (i < N_NODES * OUT_CH / 4)
        ((float4*)out)[i] = ((const float4*)g_out)[i];
}

// ---------------------------------------------------------------------------
extern "C" void kernel_launch(void* const* d_in, const int* in_sizes, int n_in,
                              void* d_out, int out_size) {
    const float* x  = (const float*)d_in[0];       // [N, 128]
    const int*   ei = (const int*)d_in[1];         // [2, E] int32 OR int64 (detected)
    const float* ew = (const float*)d_in[2];       // [E]
    const float* W  = (const float*)d_in[3];       // [128, 64]
    const float* b  = (const float*)d_in[4];       // [64]
    float* out = (float*)d_out;                    // [N, 64]
    (void)in_sizes; (void)n_in; (void)out_size;

    detect_dtype_kernel<<<1, 256>>>((const unsigned*)d_in[1]);
    deg_init_kernel<<<(N_NODES + 255) / 256, 256>>>();
    deg_accum_kernel<<<(N_EDGES + 255) / 256, 256>>>(ei, ew);
    dinv_kernel<<<(N_NODES + 255) / 256, 256>>>();
    gemm_kernel<<<(N_NODES + GEMM_ROWS - 1) / GEMM_ROWS, 256>>>(x, W);
    {
        int units = N_NODES * 16;
        init_out_kernel<<<(units + 255) / 256, 256>>>(b);
    }
    {
        long long units = (long long)N_EDGES * 16;
        scatter_kernel<<<(int)((units + 255) / 256), 256>>>(ei, ew);
    }
    {
        int units = N_NODES * OUT_CH / 4;
        copy_out_kernel<<<(units + 255) / 256, 256>>>(out);
    }
}